// round 1
// baseline (speedup 1.0000x reference)
#include <cuda_runtime.h>
#include <cstdint>
#include <math.h>

#define B_TOTAL 65536
#define HDIM 128
#define MSGD 172
#define NNODES 200000
#define TM 64

// ---------------- scratch (__device__ globals: allocation-free) ----------------
__device__ __align__(16) float g_hnew[(size_t)B_TOTAL * HDIM];     // ~33.5 MB
__device__ int   g_lastpos[NNODES];
__device__ __align__(16) float g_W1T[176 * 128];                   // k-major, zero-padded K 172->176
__device__ __align__(16) float g_W2T[128 * 128];
__device__ __align__(16) float g_WcatT[256 * 512];                 // [k][gate*128+j], gates: r,z,gx_n,gh_n

// ---------------- f32x2 packed-FMA helpers ----------------
static __device__ __forceinline__ unsigned long long bcast2(float v) {
    unsigned long long r;
    asm("mov.b64 %0, {%1, %1};" : "=l"(r) : "f"(v));
    return r;
}
static __device__ __forceinline__ void ffma2(unsigned long long& d,
                                             unsigned long long a,
                                             unsigned long long b) {
    asm("fma.rn.f32x2 %0, %1, %2, %0;" : "+l"(d) : "l"(a), "l"(b));
}
static __device__ __forceinline__ float2 unpack2(unsigned long long v) {
    float2 f;
    asm("mov.b64 {%0, %1}, %2;" : "=f"(f.x), "=f"(f.y) : "l"(v));
    return f;
}

// ---------------- prep: transpose / fuse weights ----------------
__global__ void prep_kernel(const float* __restrict__ W1, const float* __restrict__ W2,
                            const float* __restrict__ Wih, const float* __restrict__ Whh) {
    int idx = blockIdx.x * blockDim.x + threadIdx.x;
    if (idx < 176 * 128) {
        int k = idx >> 7, c = idx & 127;
        g_W1T[idx] = (k < MSGD) ? W1[c * MSGD + k] : 0.0f;
    } else if (idx < 176 * 128 + 128 * 128) {
        int j = idx - 176 * 128;
        int k = j >> 7, c = j & 127;
        g_W2T[j] = W2[c * 128 + k];
    } else if (idx < 176 * 128 + 128 * 128 + 256 * 512) {
        int j = idx - (176 * 128 + 128 * 128);
        int k = j >> 9, n = j & 511;
        int jj = n & 127, g = n >> 7;
        float v;
        if (g == 0)      v = (k < 128) ? Wih[jj * 128 + k]         : Whh[jj * 128 + (k - 128)];
        else if (g == 1) v = (k < 128) ? Wih[(128 + jj) * 128 + k] : Whh[(128 + jj) * 128 + (k - 128)];
        else if (g == 2) v = (k < 128) ? Wih[(256 + jj) * 128 + k] : 0.0f;
        else             v = (k < 128) ? 0.0f                      : Whh[(256 + jj) * 128 + (k - 128)];
        g_WcatT[j] = v;
    }
}

// ---------------- last-event-wins bookkeeping ----------------
__global__ void init_lastpos() {
    int i = blockIdx.x * blockDim.x + threadIdx.x;
    if (i < NNODES) g_lastpos[i] = -1;
}
__global__ void scatter_lastpos(const int* __restrict__ node_ids) {
    int i = blockIdx.x * blockDim.x + threadIdx.x;
    if (i < B_TOTAL) {
        int id = node_ids[i];
        id = min(max(id, 0), NNODES - 1);
        atomicMax(&g_lastpos[id], i);
    }
}

// ---------------- GEMM chunk engine ----------------
// 256 threads, warp w owns rows w*8..w*8+7, lane owns cols lane*4..lane*4+3.
// A in smem (row-major, absolute k index), W staged from global k-major scratch.
template <int KC>
static __device__ __forceinline__ void gemm_acc(
    float* s_w, const float* sA, int ldA,
    const float* gWT, int gldW, int gcol,
    int kb, int ke, unsigned long long acc[8][2],
    int tid, int r0, int c0)
{
    for (int k0 = kb; k0 < ke; k0 += KC) {
        __syncthreads();
        // stage W chunk: KC x 128, contiguous & coalesced
        for (int t = tid; t < KC * 32; t += 256) {
            int kk = t >> 5, c4 = (t & 31) << 2;
            *(float4*)&s_w[kk * 128 + c4] =
                *(const float4*)&gWT[(size_t)(k0 + kk) * gldW + gcol + c4];
        }
        __syncthreads();
#pragma unroll
        for (int k4 = 0; k4 < KC; k4 += 4) {
            float4 a[8];
#pragma unroll
            for (int i = 0; i < 8; i++)
                a[i] = *(const float4*)&sA[(r0 + i) * ldA + k0 + k4];
#pragma unroll
            for (int kk = 0; kk < 4; kk++) {
                ulonglong2 w = *(const ulonglong2*)&s_w[(k4 + kk) * 128 + c0];
#pragma unroll
                for (int i = 0; i < 8; i++) {
                    float av = ((const float*)&a[i])[kk];
                    unsigned long long ap = bcast2(av);
                    ffma2(acc[i][0], ap, w.x);
                    ffma2(acc[i][1], ap, w.y);
                }
            }
        }
    }
}

#define ZERO_ACC()                                    \
    _Pragma("unroll")                                 \
    for (int i = 0; i < 8; i++) { acc[i][0] = 0ull; acc[i][1] = 0ull; }

static __device__ __forceinline__ float sigmoidf_(float x) {
    return 1.0f / (1.0f + expf(-x));
}

// ---------------- main fused kernel: 64 batch rows per CTA ----------------
__global__ __launch_bounds__(256) void tgn_main(
    const int* __restrict__ node_ids, const float* __restrict__ messages,
    const float* __restrict__ timestamps, const float* __restrict__ memory,
    const float* __restrict__ last_update,
    const float* __restrict__ b1, const float* __restrict__ b2,
    const float* __restrict__ b_ih, const float* __restrict__ b_hh)
{
    extern __shared__ float smem[];
    float* s_msg = smem;                    // 64*176 (reused as xn later)
    float* s_pm1 = smem + 64 * 176;         // 64*128 (reused as hn later)
    float* s_ph  = s_pm1 + 64 * 128;        // 64*256 : [pm | h]
    float* s_w   = s_ph + 64 * 256;         // 44*128 weight staging
    float* s_xn  = s_msg;
    float* s_hn  = s_pm1;

    int tid = threadIdx.x;
    int warp = tid >> 5, lane = tid & 31;
    int r0 = warp * 8, c0 = lane * 4;
    int row0 = blockIdx.x * TM;

    // load messages (pad K 172->176 with zeros)
    const float4* msg4 = (const float4*)messages;
    for (int t = tid; t < 64 * 44; t += 256) {
        int r = t / 44, c = t % 44;
        float4 v = make_float4(0.f, 0.f, 0.f, 0.f);
        if (c < 43) v = msg4[(size_t)(row0 + r) * 43 + c];
        *(float4*)&s_msg[r * 176 + c * 4] = v;
    }

    // gather decayed memory h -> s_ph[:,128:256]  (4 threads per row)
    {
        int gr = tid >> 2, part = tid & 3;
        int grow = row0 + gr;
        int id = node_ids[grow];
        id = min(max(id, 0), NNODES - 1);
        float dt = timestamps[grow] - last_update[id];
        dt = fmaxf(dt, 0.0f);
        float sc = expf(-0.1f * dt);
        const float4* m4 = (const float4*)(memory + (size_t)id * HDIM);
#pragma unroll
        for (int q = 0; q < 8; q++) {
            float4 v = m4[part * 8 + q];
            v.x *= sc; v.y *= sc; v.z *= sc; v.w *= sc;
            *(float4*)&s_ph[gr * 256 + 128 + part * 32 + q * 4] = v;
        }
    }

    unsigned long long acc[8][2];

    // GEMM1: pm1 = relu(msg @ W1^T + b1)
    ZERO_ACC();
    gemm_acc<44>(s_w, s_msg, 176, g_W1T, 128, 0, 0, 176, acc, tid, r0, c0);
    {
        float4 b = *(const float4*)&b1[c0];
#pragma unroll
        for (int i = 0; i < 8; i++) {
            float2 p0 = unpack2(acc[i][0]), p1 = unpack2(acc[i][1]);
            float4 o = make_float4(fmaxf(p0.x + b.x, 0.f), fmaxf(p0.y + b.y, 0.f),
                                   fmaxf(p1.x + b.z, 0.f), fmaxf(p1.y + b.w, 0.f));
            *(float4*)&s_pm1[(r0 + i) * 128 + c0] = o;
        }
    }

    // GEMM2: pm = pm1 @ W2^T + b2 -> s_ph[:,0:128]
    ZERO_ACC();
    gemm_acc<32>(s_w, s_pm1, 128, g_W2T, 128, 0, 0, 128, acc, tid, r0, c0);
    {
        float4 b = *(const float4*)&b2[c0];
#pragma unroll
        for (int i = 0; i < 8; i++) {
            float2 p0 = unpack2(acc[i][0]), p1 = unpack2(acc[i][1]);
            float4 o = make_float4(p0.x + b.x, p0.y + b.y, p1.x + b.z, p1.y + b.w);
            *(float4*)&s_ph[(r0 + i) * 256 + c0] = o;
        }
    }

    // gx_n = pm @ W_ih[2H:]^T + b_ih[2H:]  (K = 0..128 of PH, gate col 256)
    ZERO_ACC();
    gemm_acc<32>(s_w, s_ph, 256, g_WcatT, 512, 256, 0, 128, acc, tid, r0, c0);
    {
        float4 b = *(const float4*)&b_ih[256 + c0];
#pragma unroll
        for (int i = 0; i < 8; i++) {
            float2 p0 = unpack2(acc[i][0]), p1 = unpack2(acc[i][1]);
            float4 o = make_float4(p0.x + b.x, p0.y + b.y, p1.x + b.z, p1.y + b.w);
            *(float4*)&s_xn[(r0 + i) * 128 + c0] = o;
        }
    }

    // gh_n = h @ W_hh[2H:]^T + b_hh[2H:]  (K = 128..256 of PH, gate col 384)
    ZERO_ACC();
    gemm_acc<32>(s_w, s_ph, 256, g_WcatT, 512, 384, 128, 256, acc, tid, r0, c0);
    {
        float4 b = *(const float4*)&b_hh[256 + c0];
#pragma unroll
        for (int i = 0; i < 8; i++) {
            float2 p0 = unpack2(acc[i][0]), p1 = unpack2(acc[i][1]);
            float4 o = make_float4(p0.x + b.x, p0.y + b.y, p1.x + b.z, p1.y + b.w);
            *(float4*)&s_hn[(r0 + i) * 128 + c0] = o;
        }
    }

    // r gate: full K=256 against [W_ih_r | W_hh_r]; then n = tanh(gx_n + r*gh_n)
    float nreg[8][4];
    ZERO_ACC();
    gemm_acc<32>(s_w, s_ph, 256, g_WcatT, 512, 0, 0, 256, acc, tid, r0, c0);
    {
        float4 bi = *(const float4*)&b_ih[c0];
        float4 bh = *(const float4*)&b_hh[c0];
        float bb[4] = {bi.x + bh.x, bi.y + bh.y, bi.z + bh.z, bi.w + bh.w};
#pragma unroll
        for (int i = 0; i < 8; i++) {
            float2 p0 = unpack2(acc[i][0]), p1 = unpack2(acc[i][1]);
            float g[4] = {p0.x, p0.y, p1.x, p1.y};
            float4 xn4 = *(const float4*)&s_xn[(r0 + i) * 128 + c0];
            float4 hn4 = *(const float4*)&s_hn[(r0 + i) * 128 + c0];
            float xn[4] = {xn4.x, xn4.y, xn4.z, xn4.w};
            float hn[4] = {hn4.x, hn4.y, hn4.z, hn4.w};
#pragma unroll
            for (int j = 0; j < 4; j++) {
                float r = sigmoidf_(g[j] + bb[j]);
                nreg[i][j] = tanhf(xn[j] + r * hn[j]);
            }
        }
    }

    // z gate: full K=256; h_new = (1-z)*n + z*h  -> g_hnew
    ZERO_ACC();
    gemm_acc<32>(s_w, s_ph, 256, g_WcatT, 512, 128, 0, 256, acc, tid, r0, c0);
    {
        float4 bi = *(const float4*)&b_ih[128 + c0];
        float4 bh = *(const float4*)&b_hh[128 + c0];
        float bb[4] = {bi.x + bh.x, bi.y + bh.y, bi.z + bh.z, bi.w + bh.w};
#pragma unroll
        for (int i = 0; i < 8; i++) {
            float2 p0 = unpack2(acc[i][0]), p1 = unpack2(acc[i][1]);
            float g[4] = {p0.x, p0.y, p1.x, p1.y};
            float4 h4 = *(const float4*)&s_ph[(r0 + i) * 256 + 128 + c0];
            float hv[4] = {h4.x, h4.y, h4.z, h4.w};
            float o[4];
#pragma unroll
            for (int j = 0; j < 4; j++) {
                float z = sigmoidf_(g[j] + bb[j]);
                o[j] = (1.0f - z) * nreg[i][j] + z * hv[j];
            }
            *(float4*)&g_hnew[(size_t)(row0 + r0 + i) * 128 + c0] =
                make_float4(o[0], o[1], o[2], o[3]);
        }
    }
}

// ---------------- finalize: out = memory with last-event rows replaced ----------------
__global__ __launch_bounds__(256) void finalize_kernel(const float* __restrict__ memory,
                                                       float* __restrict__ out) {
    int tid = threadIdx.x;
    int row = blockIdx.x * 8 + (tid >> 5);
    int lane = tid & 31;
    if (row < NNODES) {
        int lp = g_lastpos[row];
        const float4* src = (lp >= 0)
            ? (const float4*)&g_hnew[(size_t)lp * HDIM]
            : (const float4*)&memory[(size_t)row * HDIM];
        float4* dst = (float4*)&out[(size_t)row * HDIM];
        dst[lane] = src[lane];
    }
}

// ---------------- launch ----------------
extern "C" void kernel_launch(void* const* d_in, const int* in_sizes, int n_in,
                              void* d_out, int out_size) {
    const int*   node_ids    = (const int*)d_in[0];
    const float* messages    = (const float*)d_in[1];
    const float* timestamps  = (const float*)d_in[2];
    const float* memory      = (const float*)d_in[3];
    const float* last_update = (const float*)d_in[4];
    const float* W1          = (const float*)d_in[5];
    const float* b1          = (const float*)d_in[6];
    const float* W2          = (const float*)d_in[7];
    const float* b2          = (const float*)d_in[8];
    const float* W_ih        = (const float*)d_in[9];
    const float* W_hh        = (const float*)d_in[10];
    const float* b_ih        = (const float*)d_in[11];
    const float* b_hh        = (const float*)d_in[12];
    float* out = (float*)d_out;

    const int smem_bytes = (64 * 176 + 64 * 128 + 64 * 256 + 44 * 128) * 4; // 165,888 B
    cudaFuncSetAttribute(tgn_main, cudaFuncAttributeMaxDynamicSharedMemorySize, smem_bytes);

    const int prep_elems = 176 * 128 + 128 * 128 + 256 * 512;
    prep_kernel<<<(prep_elems + 255) / 256, 256>>>(W1, W2, W_ih, W_hh);
    init_lastpos<<<(NNODES + 255) / 256, 256>>>();
    scatter_lastpos<<<B_TOTAL / 256, 256>>>(node_ids);
    tgn_main<<<B_TOTAL / TM, 256, smem_bytes>>>(node_ids, messages, timestamps,
                                                memory, last_update,
                                                b1, b2, b_ih, b_hh);
    finalize_kernel<<<(NNODES + 7) / 8, 256>>>(memory, out);
}

// round 2
// speedup vs baseline: 1.0002x; 1.0002x over previous
#include <cuda_runtime.h>
#include <cstdint>
#include <math.h>

#define B_TOTAL 65536
#define HDIM 128
#define MSGD 172
#define NNODES 200000
#define TM 64

// ---------------- scratch (__device__ globals: allocation-free) ----------------
__device__ __align__(16) float g_hnew[(size_t)B_TOTAL * HDIM];     // ~33.5 MB
__device__ int   g_lastpos[NNODES];
__device__ __align__(16) float g_W1T[176 * 128];                   // k-major, zero-padded K 172->176
__device__ __align__(16) float g_W2T[128 * 128];
__device__ __align__(16) float g_WcatT[256 * 512];                 // [k][gate*128+j], gates: r,z,gx_n,gh_n

// ---------------- f32x2 packed-FMA helpers ----------------
static __device__ __forceinline__ unsigned long long bcast2(float v) {
    unsigned long long r;
    asm("mov.b64 %0, {%1, %1};" : "=l"(r) : "f"(v));
    return r;
}
static __device__ __forceinline__ void ffma2(unsigned long long& d,
                                             unsigned long long a,
                                             unsigned long long b) {
    asm("fma.rn.f32x2 %0, %1, %2, %0;" : "+l"(d) : "l"(a), "l"(b));
}
static __device__ __forceinline__ float2 unpack2(unsigned long long v) {
    float2 f;
    asm("mov.b64 {%0, %1}, %2;" : "=f"(f.x), "=f"(f.y) : "l"(v));
    return f;
}

// ---------------- prep: transpose / fuse weights ----------------
__global__ void prep_kernel(const float* __restrict__ W1, const float* __restrict__ W2,
                            const float* __restrict__ Wih, const float* __restrict__ Whh) {
    int idx = blockIdx.x * blockDim.x + threadIdx.x;
    if (idx < 176 * 128) {
        int k = idx >> 7, c = idx & 127;
        g_W1T[idx] = (k < MSGD) ? W1[c * MSGD + k] : 0.0f;
    } else if (idx < 176 * 128 + 128 * 128) {
        int j = idx - 176 * 128;
        int k = j >> 7, c = j & 127;
        g_W2T[j] = W2[c * 128 + k];
    } else if (idx < 176 * 128 + 128 * 128 + 256 * 512) {
        int j = idx - (176 * 128 + 128 * 128);
        int k = j >> 9, n = j & 511;
        int jj = n & 127, g = n >> 7;
        float v;
        if (g == 0)      v = (k < 128) ? Wih[jj * 128 + k]         : Whh[jj * 128 + (k - 128)];
        else if (g == 1) v = (k < 128) ? Wih[(128 + jj) * 128 + k] : Whh[(128 + jj) * 128 + (k - 128)];
        else if (g == 2) v = (k < 128) ? Wih[(256 + jj) * 128 + k] : 0.0f;
        else             v = (k < 128) ? 0.0f                      : Whh[(256 + jj) * 128 + (k - 128)];
        g_WcatT[j] = v;
    }
}

// ---------------- last-event-wins bookkeeping ----------------
__global__ void init_lastpos() {
    int i = blockIdx.x * blockDim.x + threadIdx.x;
    if (i < NNODES) g_lastpos[i] = -1;
}
__global__ void scatter_lastpos(const int* __restrict__ node_ids) {
    int i = blockIdx.x * blockDim.x + threadIdx.x;
    if (i < B_TOTAL) {
        int id = node_ids[i];
        id = min(max(id, 0), NNODES - 1);
        atomicMax(&g_lastpos[id], i);
    }
}

// ---------------- GEMM chunk engine ----------------
// 256 threads, warp w owns rows w*8..w*8+7, lane owns cols lane*4..lane*4+3.
// A in smem (row-major, absolute k index), W staged from global k-major scratch.
template <int KC>
static __device__ __forceinline__ void gemm_acc(
    float* s_w, const float* sA, int ldA,
    const float* gWT, int gldW, int gcol,
    int kb, int ke, unsigned long long acc[8][2],
    int tid, int r0, int c0)
{
    for (int k0 = kb; k0 < ke; k0 += KC) {
        __syncthreads();
        // stage W chunk: KC x 128, contiguous & coalesced
        for (int t = tid; t < KC * 32; t += 256) {
            int kk = t >> 5, c4 = (t & 31) << 2;
            *(float4*)&s_w[kk * 128 + c4] =
                *(const float4*)&gWT[(size_t)(k0 + kk) * gldW + gcol + c4];
        }
        __syncthreads();
#pragma unroll
        for (int k4 = 0; k4 < KC; k4 += 4) {
            float4 a[8];
#pragma unroll
            for (int i = 0; i < 8; i++)
                a[i] = *(const float4*)&sA[(r0 + i) * ldA + k0 + k4];
#pragma unroll
            for (int kk = 0; kk < 4; kk++) {
                ulonglong2 w = *(const ulonglong2*)&s_w[(k4 + kk) * 128 + c0];
#pragma unroll
                for (int i = 0; i < 8; i++) {
                    float av = ((const float*)&a[i])[kk];
                    unsigned long long ap = bcast2(av);
                    ffma2(acc[i][0], ap, w.x);
                    ffma2(acc[i][1], ap, w.y);
                }
            }
        }
    }
}

#define ZERO_ACC()                                    \
    _Pragma("unroll")                                 \
    for (int i = 0; i < 8; i++) { acc[i][0] = 0ull; acc[i][1] = 0ull; }

static __device__ __forceinline__ float sigmoidf_(float x) {
    return 1.0f / (1.0f + expf(-x));
}

// ---------------- main fused kernel: 64 batch rows per CTA ----------------
__global__ __launch_bounds__(256) void tgn_main(
    const int* __restrict__ node_ids, const float* __restrict__ messages,
    const float* __restrict__ timestamps, const float* __restrict__ memory,
    const float* __restrict__ last_update,
    const float* __restrict__ b1, const float* __restrict__ b2,
    const float* __restrict__ b_ih, const float* __restrict__ b_hh)
{
    extern __shared__ float smem[];
    float* s_msg = smem;                    // 64*176 (reused as xn later)
    float* s_pm1 = smem + 64 * 176;         // 64*128 (reused as hn later)
    float* s_ph  = s_pm1 + 64 * 128;        // 64*256 : [pm | h]
    float* s_w   = s_ph + 64 * 256;         // 44*128 weight staging
    float* s_xn  = s_msg;
    float* s_hn  = s_pm1;

    int tid = threadIdx.x;
    int warp = tid >> 5, lane = tid & 31;
    int r0 = warp * 8, c0 = lane * 4;
    int row0 = blockIdx.x * TM;

    // load messages (pad K 172->176 with zeros)
    const float4* msg4 = (const float4*)messages;
    for (int t = tid; t < 64 * 44; t += 256) {
        int r = t / 44, c = t % 44;
        float4 v = make_float4(0.f, 0.f, 0.f, 0.f);
        if (c < 43) v = msg4[(size_t)(row0 + r) * 43 + c];
        *(float4*)&s_msg[r * 176 + c * 4] = v;
    }

    // gather decayed memory h -> s_ph[:,128:256]  (4 threads per row)
    {
        int gr = tid >> 2, part = tid & 3;
        int grow = row0 + gr;
        int id = node_ids[grow];
        id = min(max(id, 0), NNODES - 1);
        float dt = timestamps[grow] - last_update[id];
        dt = fmaxf(dt, 0.0f);
        float sc = expf(-0.1f * dt);
        const float4* m4 = (const float4*)(memory + (size_t)id * HDIM);
#pragma unroll
        for (int q = 0; q < 8; q++) {
            float4 v = m4[part * 8 + q];
            v.x *= sc; v.y *= sc; v.z *= sc; v.w *= sc;
            *(float4*)&s_ph[gr * 256 + 128 + part * 32 + q * 4] = v;
        }
    }

    unsigned long long acc[8][2];

    // GEMM1: pm1 = relu(msg @ W1^T + b1)
    ZERO_ACC();
    gemm_acc<44>(s_w, s_msg, 176, g_W1T, 128, 0, 0, 176, acc, tid, r0, c0);
    {
        float4 b = *(const float4*)&b1[c0];
#pragma unroll
        for (int i = 0; i < 8; i++) {
            float2 p0 = unpack2(acc[i][0]), p1 = unpack2(acc[i][1]);
            float4 o = make_float4(fmaxf(p0.x + b.x, 0.f), fmaxf(p0.y + b.y, 0.f),
                                   fmaxf(p1.x + b.z, 0.f), fmaxf(p1.y + b.w, 0.f));
            *(float4*)&s_pm1[(r0 + i) * 128 + c0] = o;
        }
    }

    // GEMM2: pm = pm1 @ W2^T + b2 -> s_ph[:,0:128]
    ZERO_ACC();
    gemm_acc<32>(s_w, s_pm1, 128, g_W2T, 128, 0, 0, 128, acc, tid, r0, c0);
    {
        float4 b = *(const float4*)&b2[c0];
#pragma unroll
        for (int i = 0; i < 8; i++) {
            float2 p0 = unpack2(acc[i][0]), p1 = unpack2(acc[i][1]);
            float4 o = make_float4(p0.x + b.x, p0.y + b.y, p1.x + b.z, p1.y + b.w);
            *(float4*)&s_ph[(r0 + i) * 256 + c0] = o;
        }
    }

    // gx_n = pm @ W_ih[2H:]^T + b_ih[2H:]  (K = 0..128 of PH, gate col 256)
    ZERO_ACC();
    gemm_acc<32>(s_w, s_ph, 256, g_WcatT, 512, 256, 0, 128, acc, tid, r0, c0);
    {
        float4 b = *(const float4*)&b_ih[256 + c0];
#pragma unroll
        for (int i = 0; i < 8; i++) {
            float2 p0 = unpack2(acc[i][0]), p1 = unpack2(acc[i][1]);
            float4 o = make_float4(p0.x + b.x, p0.y + b.y, p1.x + b.z, p1.y + b.w);
            *(float4*)&s_xn[(r0 + i) * 128 + c0] = o;
        }
    }

    // gh_n = h @ W_hh[2H:]^T + b_hh[2H:]  (K = 128..256 of PH, gate col 384)
    ZERO_ACC();
    gemm_acc<32>(s_w, s_ph, 256, g_WcatT, 512, 384, 128, 256, acc, tid, r0, c0);
    {
        float4 b = *(const float4*)&b_hh[256 + c0];
#pragma unroll
        for (int i = 0; i < 8; i++) {
            float2 p0 = unpack2(acc[i][0]), p1 = unpack2(acc[i][1]);
            float4 o = make_float4(p0.x + b.x, p0.y + b.y, p1.x + b.z, p1.y + b.w);
            *(float4*)&s_hn[(r0 + i) * 128 + c0] = o;
        }
    }

    // r gate: full K=256 against [W_ih_r | W_hh_r]; then n = tanh(gx_n + r*gh_n)
    float nreg[8][4];
    ZERO_ACC();
    gemm_acc<32>(s_w, s_ph, 256, g_WcatT, 512, 0, 0, 256, acc, tid, r0, c0);
    {
        float4 bi = *(const float4*)&b_ih[c0];
        float4 bh = *(const float4*)&b_hh[c0];
        float bb[4] = {bi.x + bh.x, bi.y + bh.y, bi.z + bh.z, bi.w + bh.w};
#pragma unroll
        for (int i = 0; i < 8; i++) {
            float2 p0 = unpack2(acc[i][0]), p1 = unpack2(acc[i][1]);
            float g[4] = {p0.x, p0.y, p1.x, p1.y};
            float4 xn4 = *(const float4*)&s_xn[(r0 + i) * 128 + c0];
            float4 hn4 = *(const float4*)&s_hn[(r0 + i) * 128 + c0];
            float xn[4] = {xn4.x, xn4.y, xn4.z, xn4.w};
            float hn[4] = {hn4.x, hn4.y, hn4.z, hn4.w};
#pragma unroll
            for (int j = 0; j < 4; j++) {
                float r = sigmoidf_(g[j] + bb[j]);
                nreg[i][j] = tanhf(xn[j] + r * hn[j]);
            }
        }
    }

    // z gate: full K=256; h_new = (1-z)*n + z*h  -> g_hnew
    ZERO_ACC();
    gemm_acc<32>(s_w, s_ph, 256, g_WcatT, 512, 128, 0, 256, acc, tid, r0, c0);
    {
        float4 bi = *(const float4*)&b_ih[128 + c0];
        float4 bh = *(const float4*)&b_hh[128 + c0];
        float bb[4] = {bi.x + bh.x, bi.y + bh.y, bi.z + bh.z, bi.w + bh.w};
#pragma unroll
        for (int i = 0; i < 8; i++) {
            float2 p0 = unpack2(acc[i][0]), p1 = unpack2(acc[i][1]);
            float g[4] = {p0.x, p0.y, p1.x, p1.y};
            float4 h4 = *(const float4*)&s_ph[(r0 + i) * 256 + 128 + c0];
            float hv[4] = {h4.x, h4.y, h4.z, h4.w};
            float o[4];
#pragma unroll
            for (int j = 0; j < 4; j++) {
                float z = sigmoidf_(g[j] + bb[j]);
                o[j] = (1.0f - z) * nreg[i][j] + z * hv[j];
            }
            *(float4*)&g_hnew[(size_t)(row0 + r0 + i) * 128 + c0] =
                make_float4(o[0], o[1], o[2], o[3]);
        }
    }
}

// ---------------- finalize: out = memory with last-event rows replaced ----------------
__global__ __launch_bounds__(256) void finalize_kernel(const float* __restrict__ memory,
                                                       float* __restrict__ out) {
    int tid = threadIdx.x;
    int row = blockIdx.x * 8 + (tid >> 5);
    int lane = tid & 31;
    if (row < NNODES) {
        int lp = g_lastpos[row];
        const float4* src = (lp >= 0)
            ? (const float4*)&g_hnew[(size_t)lp * HDIM]
            : (const float4*)&memory[(size_t)row * HDIM];
        float4* dst = (float4*)&out[(size_t)row * HDIM];
        dst[lane] = src[lane];
    }
}

// ---------------- launch ----------------
extern "C" void kernel_launch(void* const* d_in, const int* in_sizes, int n_in,
                              void* d_out, int out_size) {
    const int*   node_ids    = (const int*)d_in[0];
    const float* messages    = (const float*)d_in[1];
    const float* timestamps  = (const float*)d_in[2];
    const float* memory      = (const float*)d_in[3];
    const float* last_update = (const float*)d_in[4];
    const float* W1          = (const float*)d_in[5];
    const float* b1          = (const float*)d_in[6];
    const float* W2          = (const float*)d_in[7];
    const float* b2          = (const float*)d_in[8];
    const float* W_ih        = (const float*)d_in[9];
    const float* W_hh        = (const float*)d_in[10];
    const float* b_ih        = (const float*)d_in[11];
    const float* b_hh        = (const float*)d_in[12];
    float* out = (float*)d_out;

    const int smem_bytes = (64 * 176 + 64 * 128 + 64 * 256 + 44 * 128) * 4; // 165,888 B
    cudaFuncSetAttribute(tgn_main, cudaFuncAttributeMaxDynamicSharedMemorySize, smem_bytes);

    const int prep_elems = 176 * 128 + 128 * 128 + 256 * 512;
    prep_kernel<<<(prep_elems + 255) / 256, 256>>>(W1, W2, W_ih, W_hh);
    init_lastpos<<<(NNODES + 255) / 256, 256>>>();
    scatter_lastpos<<<B_TOTAL / 256, 256>>>(node_ids);
    tgn_main<<<B_TOTAL / TM, 256, smem_bytes>>>(node_ids, messages, timestamps,
                                                memory, last_update,
                                                b1, b2, b_ih, b_hh);
    finalize_kernel<<<(NNODES + 7) / 8, 256>>>(memory, out);
}